// round 2
// baseline (speedup 1.0000x reference)
#include <cuda_runtime.h>
#include <math.h>

#define NXY   36864      // 192*192 pixels
#define ETL   16
#define NDICT 4000
#define NSLOT 8          // number of SE (kept) columns; data-driven, padded with -1

// Scratch (no allocations allowed): compressed normalized dictionary + norms.
__device__ float g_db[NDICT * NSLOT];
__device__ float g_d2[NDICT];
__device__ int   g_cols[NSLOT];

// ---------------------------------------------------------------------------
// Kernel 0: derive kept-column indices from delta_t_r2p_ms.
// mask[k] = (delta_ms[k] * 1e-3 < 1e-3)  (reference semantics)
// ---------------------------------------------------------------------------
__global__ void setup_cols_kernel(const float* __restrict__ delta_ms) {
    if (threadIdx.x == 0 && blockIdx.x == 0) {
        int j = 0;
        for (int k = 0; k < ETL; k++) {
            if (delta_ms[k] * 1e-3f < 1e-3f && j < NSLOT) {
                g_cols[j++] = k;
            }
        }
        for (; j < NSLOT; j++) g_cols[j] = -1;  // padded slots contribute zeros
    }
}

// ---------------------------------------------------------------------------
// Kernel 1: compress + normalize dictionary rows over kept columns.
//   db = nan_to_num( (db_mag * mask) / ||db_mag * mask|| )
//   d2 = sum(db*db)  (== reference's d2)
// ---------------------------------------------------------------------------
__global__ void prep_dict_kernel(const float* __restrict__ db_mag) {
    int a = blockIdx.x * blockDim.x + threadIdx.x;
    if (a >= NDICT) return;

    float v[NSLOT];
    float n2 = 0.0f;
#pragma unroll
    for (int j = 0; j < NSLOT; j++) {
        int c = g_cols[j];
        float x = (c >= 0) ? db_mag[a * ETL + c] : 0.0f;
        v[j] = x;
        n2 = fmaf(x, x, n2);
    }
    // nan_to_num(x / norm): norm==0 -> nan -> 0; norm inf -> 0.
    float inv = 0.0f;
    if (n2 > 0.0f) {
        float nrm = sqrtf(n2);
        float r = 1.0f / nrm;
        if (isfinite(r)) inv = r;
    }
    float d2 = 0.0f;
#pragma unroll
    for (int j = 0; j < NSLOT; j++) {
        float s = v[j] * inv;
        g_db[a * NSLOT + j] = s;
        d2 = fmaf(s, s, d2);
    }
    g_d2[a] = d2;
}

// ---------------------------------------------------------------------------
// Kernel 2: per-pixel dictionary match.
// One thread per pixel; whole compressed dictionary staged in dynamic SMEM
// (broadcast LDS -> conflict-free). Tracks clamped dist^2 with strict < in
// ascending atom order -> identical first-index argmin semantics as jnp.argmin.
// ---------------------------------------------------------------------------
__global__ void __launch_bounds__(256, 1) match_kernel(
    const float* __restrict__ sig,     // [NXY, ETL]
    const float* __restrict__ t2s,     // [NDICT]
    const float* __restrict__ b1s,     // [NDICT]
    float* __restrict__ out)           // [3*NXY]: t2 | b1 | min_dist
{
    extern __shared__ float sm[];      // [NDICT*NSLOT] db, then [NDICT] d2
    float* sdb = sm;
    float* sd2 = sm + NDICT * NSLOT;

    // Cooperative vectorized staging of the dictionary
    {
        const float4* g4 = (const float4*)g_db;
        float4* s4 = (float4*)sdb;
        const int nvec = NDICT * NSLOT / 4;  // 8000
        for (int i = threadIdx.x; i < nvec; i += blockDim.x) s4[i] = g4[i];
        for (int i = threadIdx.x; i < NDICT; i += blockDim.x) sd2[i] = g_d2[i];
    }
    __syncthreads();

    const int n = blockIdx.x * blockDim.x + threadIdx.x;  // NXY == 144*256 exactly

    // Gather kept signal columns, normalize (nan_to_num semantics).
    // normalize(normalize(x) * mask) == normalize(x * mask) up to fp rounding;
    // the zero-norm cases coincide (||x||=0 => masked vec = 0 => s = 0).
    float m[NSLOT];
    float nm2 = 0.0f;
#pragma unroll
    for (int j = 0; j < NSLOT; j++) {
        int c = g_cols[j];
        float v = (c >= 0) ? sig[n * ETL + c] : 0.0f;
        m[j] = v;
        nm2 = fmaf(v, v, nm2);
    }
    float inv = 0.0f;
    if (nm2 > 0.0f) {
        float r = 1.0f / sqrtf(nm2);
        if (isfinite(r)) inv = r;
    }
    float s0, s1, s2v, s3, s4, s5, s6, s7;
    s0 = m[0] * inv; s1 = m[1] * inv; s2v = m[2] * inv; s3 = m[3] * inv;
    s4 = m[4] * inv; s5 = m[5] * inv; s6  = m[6] * inv; s7 = m[7] * inv;
    float s2 = 0.0f;
    s2 = fmaf(s0, s0, s2); s2 = fmaf(s1, s1, s2);
    s2 = fmaf(s2v, s2v, s2); s2 = fmaf(s3, s3, s2);
    s2 = fmaf(s4, s4, s2); s2 = fmaf(s5, s5, s2);
    s2 = fmaf(s6, s6, s2); s2 = fmaf(s7, s7, s2);

    float best = 3.402823466e38f;
    int bidx = 0;

    const float4* sdb4 = (const float4*)sdb;
#pragma unroll 4
    for (int a = 0; a < NDICT; a++) {
        float4 da = sdb4[a * 2];
        float4 db = sdb4[a * 2 + 1];
        float dot = da.x * s0;
        dot = fmaf(da.y, s1, dot);
        dot = fmaf(da.z, s2v, dot);
        dot = fmaf(da.w, s3, dot);
        dot = fmaf(db.x, s4, dot);
        dot = fmaf(db.y, s5, dot);
        dot = fmaf(db.z, s6, dot);
        dot = fmaf(db.w, s7, dot);
        float dist2 = fmaf(-2.0f, dot, sd2[a] + s2);
        dist2 = fmaxf(dist2, 0.0f);          // clamp BEFORE compare: matches
        if (dist2 < best) {                  // argmin-over-dist tie semantics
            best = dist2;
            bidx = a;
        }
    }

    out[n]           = t2s[bidx];
    out[NXY + n]     = b1s[bidx];
    out[2 * NXY + n] = sqrtf(best);
}

// ---------------------------------------------------------------------------
extern "C" void kernel_launch(void* const* d_in, const int* in_sizes, int n_in,
                              void* d_out, int out_size) {
    const float* slice_signal = (const float*)d_in[0];  // [192,192,16]
    const float* db_mag       = (const float*)d_in[1];  // [4000,16]
    const float* db_t2s_s     = (const float*)d_in[2];  // [4000]
    const float* db_b1s       = (const float*)d_in[3];  // [4000]
    const float* delta_ms     = (const float*)d_in[4];  // [16]
    float* out = (float*)d_out;

    const int smem_bytes = (NDICT * NSLOT + NDICT) * (int)sizeof(float);  // 144000
    cudaFuncSetAttribute(match_kernel,
                         cudaFuncAttributeMaxDynamicSharedMemorySize, smem_bytes);

    setup_cols_kernel<<<1, 32>>>(delta_ms);
    prep_dict_kernel<<<(NDICT + 127) / 128, 128>>>(db_mag);
    match_kernel<<<NXY / 256, 256, smem_bytes>>>(slice_signal, db_t2s_s, db_b1s, out);
}

// round 4
// speedup vs baseline: 1.2714x; 1.2714x over previous
#include <cuda_runtime.h>
#include <math.h>
#include <float.h>
#include <stdint.h>

#define NXY   36864      // 192*192 pixels
#define ETL   16
#define NDICT 4000
#define NPAIR (NDICT / 2)   // 2000 atom pairs
#define NSLOT 8             // SE (kept) columns; data-driven, padded with -1
#define REC_F 20            // floats per pair record (80 bytes, 16B aligned)

// Packed dictionary records: per pair p (atoms 2p, 2p+1):
//  [0..15]: (w_even[j], w_odd[j]) for j=0..7, w = 2 * normalized db value
//  [16,17]: (bias_even, bias_odd) = (-d2_even, -d2_odd)
//  [18,19]: pad
__device__ __align__(16) float g_dbp[NPAIR * REC_F];

// ---- packed f32x2 helpers (Blackwell FFMA2 path) ------------------------
#define FMA_F32X2(d, a, b, c) \
    asm("fma.rn.f32x2 %0, %1, %2, %3;" : "=l"(d) : "l"(a), "l"(b), "l"(c))
#define PACK_F32X2(out, lo, hi) \
    asm("mov.b64 %0, {%1, %2};" : "=l"(out) : "f"(lo), "f"(hi))
#define UNPACK_F32X2(lo, hi, in) \
    asm("mov.b64 {%0, %1}, %2;" : "=f"(lo), "=f"(hi) : "l"(in))

__device__ __forceinline__ void get_cols(const float* __restrict__ delta_ms,
                                         int* cols) {
    int j = 0;
    for (int k = 0; k < ETL; k++) {
        if (delta_ms[k] * 1e-3f < 1e-3f && j < NSLOT) cols[j++] = k;
    }
    for (; j < NSLOT; j++) cols[j] = -1;
}

// ---------------------------------------------------------------------------
// Kernel 1: build packed atom-pair records (normalization identical to ref:
// db = nan_to_num((db_mag*mask)/||db_mag*mask||); w = 2*db; bias = -sum(db^2))
// ---------------------------------------------------------------------------
__global__ void prep_dict_kernel(const float* __restrict__ db_mag,
                                 const float* __restrict__ delta_ms) {
    int cols[NSLOT];
    get_cols(delta_ms, cols);

    int p = blockIdx.x * blockDim.x + threadIdx.x;
    if (p >= NPAIR) return;

    float w[2][NSLOT];
    float bias[2];
#pragma unroll
    for (int t = 0; t < 2; t++) {
        int a = 2 * p + t;
        float v[NSLOT];
        float n2 = 0.0f;
#pragma unroll
        for (int j = 0; j < NSLOT; j++) {
            int c = cols[j];
            float x = (c >= 0) ? db_mag[a * ETL + c] : 0.0f;
            v[j] = x;
            n2 = fmaf(x, x, n2);
        }
        float inv = 0.0f;
        if (n2 > 0.0f) {
            float r = 1.0f / sqrtf(n2);
            if (isfinite(r)) inv = r;
        }
        float d2 = 0.0f;
#pragma unroll
        for (int j = 0; j < NSLOT; j++) {
            float s = v[j] * inv;
            w[t][j] = 2.0f * s;   // exact scaling by 2
            d2 = fmaf(s, s, d2);
        }
        bias[t] = -d2;
    }

    float* rec = g_dbp + p * REC_F;
#pragma unroll
    for (int j = 0; j < NSLOT; j++) {
        rec[2 * j]     = w[0][j];
        rec[2 * j + 1] = w[1][j];
    }
    rec[16] = bias[0];
    rec[17] = bias[1];
    rec[18] = 0.0f;
    rec[19] = 0.0f;
}

// ---------------------------------------------------------------------------
// Kernel 2: per-pixel match. One thread per pixel; whole packed dictionary
// (160 KB) staged in dynamic SMEM (broadcast LDS, conflict-free).
// score = 2*dot - d2  (argmax score == argmin clamped dist^2, tie-equivalent)
// ---------------------------------------------------------------------------
__global__ void __launch_bounds__(256, 1) match_kernel(
    const float* __restrict__ sig,       // [NXY, ETL]
    const float* __restrict__ t2s,       // [NDICT]
    const float* __restrict__ b1s,       // [NDICT]
    const float* __restrict__ delta_ms,  // [ETL]
    float* __restrict__ out)             // [3*NXY]: t2 | b1 | min_dist
{
    extern __shared__ __align__(16) float sm[];   // [NPAIR*REC_F] = 160 KB

    // Cooperative vectorized staging of the packed dictionary
    {
        const float4* g4 = (const float4*)g_dbp;
        float4* s4 = (float4*)sm;
        const int nvec = NPAIR * REC_F / 4;   // 10000
        for (int i = threadIdx.x; i < nvec; i += blockDim.x) s4[i] = g4[i];
    }

    int cols[NSLOT];
    get_cols(delta_ms, cols);

    const int n = blockIdx.x * blockDim.x + threadIdx.x;  // NXY == 144*256

    // Gather kept signal columns, normalize (nan_to_num semantics).
    float m[NSLOT];
    float nm2 = 0.0f;
#pragma unroll
    for (int j = 0; j < NSLOT; j++) {
        int c = cols[j];
        float v = (c >= 0) ? sig[n * ETL + c] : 0.0f;
        m[j] = v;
        nm2 = fmaf(v, v, nm2);
    }
    float inv = 0.0f;
    if (nm2 > 0.0f) {
        float r = 1.0f / sqrtf(nm2);
        if (isfinite(r)) inv = r;
    }
    float s2 = 0.0f;
    uint64_t sp[NSLOT];   // (s_j, s_j) packed pairs
#pragma unroll
    for (int j = 0; j < NSLOT; j++) {
        float s = m[j] * inv;
        s2 = fmaf(s, s, s2);
        PACK_F32X2(sp[j], s, s);
    }

    __syncthreads();

    float bestE = -FLT_MAX, bestO = -FLT_MAX;
    int idxE = 0, idxO = 0;

    const char* base = (const char*)sm;
#pragma unroll 4
    for (int p = 0; p < NPAIR; p++) {
        const ulonglong2* r = (const ulonglong2*)(base + p * 80);
        ulonglong2 q0 = r[0];   // (w0 pair, w1 pair)
        ulonglong2 q1 = r[1];   // (w2 pair, w3 pair)
        ulonglong2 q2 = r[2];   // (w4 pair, w5 pair)
        ulonglong2 q3 = r[3];   // (w6 pair, w7 pair)
        uint64_t acc = *(const unsigned long long*)(base + p * 80 + 64); // bias pair

        FMA_F32X2(acc, q0.x, sp[0], acc);
        FMA_F32X2(acc, q0.y, sp[1], acc);
        FMA_F32X2(acc, q1.x, sp[2], acc);
        FMA_F32X2(acc, q1.y, sp[3], acc);
        FMA_F32X2(acc, q2.x, sp[4], acc);
        FMA_F32X2(acc, q2.y, sp[5], acc);
        FMA_F32X2(acc, q3.x, sp[6], acc);
        FMA_F32X2(acc, q3.y, sp[7], acc);

        float lo, hi;
        UNPACK_F32X2(lo, hi, acc);
        if (lo > bestE) { bestE = lo; idxE = p; }   // strict > : first index
        if (hi > bestO) { bestO = hi; idxO = p; }
    }

    // Merge lanes: even atom has the lower global index -> wins exact ties.
    int bidx;
    float bestScore;
    if (bestO > bestE) { bidx = 2 * idxO + 1; bestScore = bestO; }
    else               { bidx = 2 * idxE;     bestScore = bestE; }

    float dist2 = fmaxf(s2 - bestScore, 0.0f);
    out[n]           = t2s[bidx];
    out[NXY + n]     = b1s[bidx];
    out[2 * NXY + n] = sqrtf(dist2);
}

// ---------------------------------------------------------------------------
extern "C" void kernel_launch(void* const* d_in, const int* in_sizes, int n_in,
                              void* d_out, int out_size) {
    const float* slice_signal = (const float*)d_in[0];  // [192,192,16]
    const float* db_mag       = (const float*)d_in[1];  // [4000,16]
    const float* db_t2s_s     = (const float*)d_in[2];  // [4000]
    const float* db_b1s       = (const float*)d_in[3];  // [4000]
    const float* delta_ms     = (const float*)d_in[4];  // [16]
    float* out = (float*)d_out;

    const int smem_bytes = NPAIR * REC_F * (int)sizeof(float);  // 160000
    cudaFuncSetAttribute(match_kernel,
                         cudaFuncAttributeMaxDynamicSharedMemorySize, smem_bytes);

    prep_dict_kernel<<<(NPAIR + 127) / 128, 128>>>(db_mag, delta_ms);
    match_kernel<<<NXY / 256, 256, smem_bytes>>>(slice_signal, db_t2s_s,
                                                 db_b1s, delta_ms, out);
}

// round 5
// speedup vs baseline: 1.9483x; 1.5324x over previous
#include <cuda_runtime.h>
#include <math.h>
#include <float.h>
#include <stdint.h>

#define NXY    36864      // 192*192 pixels
#define ETL    16
#define NDICT  4000
#define NPAIR  2000       // atom pairs
#define NSLOT  8          // SE (kept) columns; data-driven, padded with -1
#define REC_F  20         // floats per pair record (80 bytes, 16B aligned)
#define NQ     4          // dictionary quarters (CTA split)
#define PAIRS_Q (NPAIR / NQ)   // 500 pairs per quarter
#define PX     4          // pixels per thread
#define TPB    256

// Packed dictionary records (pair p = atoms 2p, 2p+1):
//  [0..15]: (w_even[j], w_odd[j]) j=0..7, w = 2 * normalized db value
//  [16,17]: (-d2_even, -d2_odd)   [18,19]: pad
__device__ __align__(16) float g_dbp[NPAIR * REC_F];
// Cross-CTA merge scratch: per-pixel best key (monotone score | inv atom idx)
__device__ unsigned long long g_best[NXY];

// ---- packed f32x2 helpers (Blackwell FFMA2 path) ------------------------
#define FMA_F32X2(d, a, b, c) \
    asm("fma.rn.f32x2 %0, %1, %2, %3;" : "=l"(d) : "l"(a), "l"(b), "l"(c))
#define PACK_F32X2(out, lo, hi) \
    asm("mov.b64 %0, {%1, %2};" : "=l"(out) : "f"(lo), "f"(hi))
#define UNPACK_F32X2(lo, hi, in) \
    asm("mov.b64 {%0, %1}, %2;" : "=f"(lo), "=f"(hi) : "l"(in))

__device__ __forceinline__ void get_cols(const float* __restrict__ delta_ms,
                                         int* cols) {
    int j = 0;
    for (int k = 0; k < ETL; k++) {
        if (delta_ms[k] * 1e-3f < 1e-3f && j < NSLOT) cols[j++] = k;
    }
    for (; j < NSLOT; j++) cols[j] = -1;
}

// order-isomorphic uint32 for float compare
__device__ __forceinline__ unsigned int fmono(float f) {
    unsigned int u = __float_as_uint(f);
    return (u & 0x80000000u) ? ~u : (u | 0x80000000u);
}
__device__ __forceinline__ float fmono_inv(unsigned int u) {
    return (u & 0x80000000u) ? __uint_as_float(u ^ 0x80000000u)
                             : __uint_as_float(~u);
}

// normalized signal (nan_to_num semantics), returns s2, fills packed (s,s)
__device__ __forceinline__ float load_signal(const float* __restrict__ sig,
                                             int n, const int* cols,
                                             uint64_t* sp) {
    float m[NSLOT];
    float nm2 = 0.0f;
#pragma unroll
    for (int j = 0; j < NSLOT; j++) {
        int c = cols[j];
        float v = (c >= 0) ? sig[n * ETL + c] : 0.0f;
        m[j] = v;
        nm2 = fmaf(v, v, nm2);
    }
    float inv = 0.0f;
    if (nm2 > 0.0f) {
        float r = 1.0f / sqrtf(nm2);
        if (isfinite(r)) inv = r;
    }
    float s2 = 0.0f;
#pragma unroll
    for (int j = 0; j < NSLOT; j++) {
        float s = m[j] * inv;
        s2 = fmaf(s, s, s2);
        PACK_F32X2(sp[j], s, s);
    }
    return s2;
}

// scores of a record (2 atoms) against one packed signal; bit-deterministic
__device__ __forceinline__ void rec_scores(const char* rec,
                                           const uint64_t* sp,
                                           float& lo, float& hi) {
    const ulonglong2* r = (const ulonglong2*)rec;
    ulonglong2 q0 = r[0];
    ulonglong2 q1 = r[1];
    ulonglong2 q2 = r[2];
    ulonglong2 q3 = r[3];
    uint64_t acc = *(const unsigned long long*)(rec + 64);
    FMA_F32X2(acc, q0.x, sp[0], acc);
    FMA_F32X2(acc, q0.y, sp[1], acc);
    FMA_F32X2(acc, q1.x, sp[2], acc);
    FMA_F32X2(acc, q1.y, sp[3], acc);
    FMA_F32X2(acc, q2.x, sp[4], acc);
    FMA_F32X2(acc, q2.y, sp[5], acc);
    FMA_F32X2(acc, q3.x, sp[6], acc);
    FMA_F32X2(acc, q3.y, sp[7], acc);
    UNPACK_F32X2(lo, hi, acc);
}

// ---------------------------------------------------------------------------
// Kernel 1: zero merge scratch + build packed atom-pair records.
// ---------------------------------------------------------------------------
__global__ void prep_kernel(const float* __restrict__ db_mag,
                            const float* __restrict__ delta_ms) {
    int t = blockIdx.x * blockDim.x + threadIdx.x;
    if (t < NXY) g_best[t] = 0ULL;
    if (t >= NPAIR) return;

    int cols[NSLOT];
    get_cols(delta_ms, cols);

    float w[2][NSLOT];
    float bias[2];
#pragma unroll
    for (int s = 0; s < 2; s++) {
        int a = 2 * t + s;
        float v[NSLOT];
        float n2 = 0.0f;
#pragma unroll
        for (int j = 0; j < NSLOT; j++) {
            int c = cols[j];
            float x = (c >= 0) ? db_mag[a * ETL + c] : 0.0f;
            v[j] = x;
            n2 = fmaf(x, x, n2);
        }
        float inv = 0.0f;
        if (n2 > 0.0f) {
            float r = 1.0f / sqrtf(n2);
            if (isfinite(r)) inv = r;
        }
        float d2 = 0.0f;
#pragma unroll
        for (int j = 0; j < NSLOT; j++) {
            float sc = v[j] * inv;
            w[s][j] = 2.0f * sc;
            d2 = fmaf(sc, sc, d2);
        }
        bias[s] = -d2;
    }
    float* rec = g_dbp + t * REC_F;
#pragma unroll
    for (int j = 0; j < NSLOT; j++) {
        rec[2 * j]     = w[0][j];
        rec[2 * j + 1] = w[1][j];
    }
    rec[16] = bias[0];
    rec[17] = bias[1];
    rec[18] = 0.0f;
    rec[19] = 0.0f;
}

// ---------------------------------------------------------------------------
// Kernel 2: match. grid = 36 pixel-groups x 4 dict-quarters.
// Each thread: 4 pixels, scans 500 pairs (quarter dict in 40 KB SMEM).
// Grouped max per iteration (4 atoms), exact recompute of winner at the end,
// cross-CTA merge via atomicMax on an order-isomorphic key.
// ---------------------------------------------------------------------------
__global__ void __launch_bounds__(TPB, 1) match_kernel(
    const float* __restrict__ sig,       // [NXY, ETL]
    const float* __restrict__ delta_ms)  // [ETL]
{
    extern __shared__ __align__(16) float sm[];   // PAIRS_Q*REC_F = 40 KB

    const int group = blockIdx.x >> 2;   // 0..35
    const int q     = blockIdx.x & 3;    // dict quarter

    // Stage this quarter's records
    {
        const float4* g4 = (const float4*)(g_dbp + q * PAIRS_Q * REC_F);
        float4* s4 = (float4*)sm;
        const int nvec = PAIRS_Q * REC_F / 4;   // 2500
        for (int i = threadIdx.x; i < nvec; i += TPB) s4[i] = g4[i];
    }

    int cols[NSLOT];
    get_cols(delta_ms, cols);

    int n[PX];
    uint64_t sp[PX][NSLOT];
#pragma unroll
    for (int u = 0; u < PX; u++) {
        n[u] = group * (TPB * PX) + u * TPB + threadIdx.x;
        (void)load_signal(sig, n[u], cols, sp[u]);
    }

    __syncthreads();

    float best[PX];
    int bit[PX];
#pragma unroll
    for (int u = 0; u < PX; u++) { best[u] = -FLT_MAX; bit[u] = 0; }

    const char* base = (const char*)sm;
#pragma unroll 2
    for (int i = 0; i < PAIRS_Q / 2; i++) {   // 250 iterations, 4 atoms each
        const char* r0 = base + (2 * i) * 80;
        const char* r1 = r0 + 80;
#pragma unroll
        for (int u = 0; u < PX; u++) {
            float s0, s1, s2a, s3;
            rec_scores(r0, sp[u], s0, s1);
            rec_scores(r1, sp[u], s2a, s3);
            float m = fmaxf(fmaxf(s0, s1), fmaxf(s2a, s3));
            if (m > best[u]) { best[u] = m; bit[u] = i; }  // first iter wins ties
        }
    }

    // Recompute the winning iteration's scores (identical op order -> identical
    // bits) and pick the first matching atom index; merge across CTAs.
#pragma unroll
    for (int u = 0; u < PX; u++) {
        int i = bit[u];
        const char* r0 = base + (2 * i) * 80;
        const char* r1 = r0 + 80;
        float s0, s1, s2a, s3;
        rec_scores(r0, sp[u], s0, s1);
        rec_scores(r1, sp[u], s2a, s3);
        int j = (s0 == best[u]) ? 0 : (s1 == best[u]) ? 1
              : (s2a == best[u]) ? 2 : 3;
        int atom = q * (2 * PAIRS_Q) + 4 * i + j;   // global atom index
        unsigned long long key =
            ((unsigned long long)fmono(best[u]) << 32)
            | (unsigned long long)(65535 - atom);
        atomicMax(&g_best[n[u]], key);
    }
}

// ---------------------------------------------------------------------------
// Kernel 3: finalize — decode merged keys, recompute s2, write outputs.
// ---------------------------------------------------------------------------
__global__ void finalize_kernel(const float* __restrict__ sig,
                                const float* __restrict__ t2s,
                                const float* __restrict__ b1s,
                                const float* __restrict__ delta_ms,
                                float* __restrict__ out) {
    int n = blockIdx.x * blockDim.x + threadIdx.x;
    if (n >= NXY) return;

    int cols[NSLOT];
    get_cols(delta_ms, cols);

    float nm2 = 0.0f;
    float m[NSLOT];
#pragma unroll
    for (int j = 0; j < NSLOT; j++) {
        int c = cols[j];
        float v = (c >= 0) ? sig[n * ETL + c] : 0.0f;
        m[j] = v;
        nm2 = fmaf(v, v, nm2);
    }
    float inv = 0.0f;
    if (nm2 > 0.0f) {
        float r = 1.0f / sqrtf(nm2);
        if (isfinite(r)) inv = r;
    }
    float s2 = 0.0f;
#pragma unroll
    for (int j = 0; j < NSLOT; j++) {
        float s = m[j] * inv;
        s2 = fmaf(s, s, s2);
    }

    unsigned long long key = g_best[n];
    int atom = 65535 - (int)(key & 0xFFFFULL);
    float score = fmono_inv((unsigned int)(key >> 32));
    float dist2 = fmaxf(s2 - score, 0.0f);

    out[n]           = t2s[atom];
    out[NXY + n]     = b1s[atom];
    out[2 * NXY + n] = sqrtf(dist2);
}

// ---------------------------------------------------------------------------
extern "C" void kernel_launch(void* const* d_in, const int* in_sizes, int n_in,
                              void* d_out, int out_size) {
    const float* slice_signal = (const float*)d_in[0];  // [192,192,16]
    const float* db_mag       = (const float*)d_in[1];  // [4000,16]
    const float* db_t2s_s     = (const float*)d_in[2];  // [4000]
    const float* db_b1s       = (const float*)d_in[3];  // [4000]
    const float* delta_ms     = (const float*)d_in[4];  // [16]
    float* out = (float*)d_out;

    const int smem_bytes = PAIRS_Q * REC_F * (int)sizeof(float);  // 40000
    cudaFuncSetAttribute(match_kernel,
                         cudaFuncAttributeMaxDynamicSharedMemorySize, smem_bytes);

    prep_kernel<<<(NXY + 127) / 128, 128>>>(db_mag, delta_ms);
    match_kernel<<<144, TPB, smem_bytes>>>(slice_signal, delta_ms);
    finalize_kernel<<<(NXY + 255) / 256, 256>>>(slice_signal, db_t2s_s,
                                                db_b1s, delta_ms, out);
}